// round 12
// baseline (speedup 1.0000x reference)
#include <cuda_runtime.h>
#include <cuda_fp16.h>
#include <cstdint>
#include <cstddef>

#define S_    256
#define NSEQ  256
#define C_    32
#define CZ    128
#define SC    8192      /* S*C */
#define KOUT  1024      /* C*C */
#define JPAN  128       /* j-values per panel; O-panel = 67 MB < L2 */

// ----- scratch (__device__ globals; allocation-free rule) -------------------
__device__ __align__(16) __half g_A[SC * NSEQ];               // 4 MB, K-major (unscaled)
__device__ __align__(16) __half g_B[SC * NSEQ];               // 4 MB
__device__ __align__(16) __half g_O[(size_t)S_ * S_ * KOUT];  // 134 MB
__device__ __align__(16) __half g_W[CZ * KOUT];               // 256 KB

#define DEVINL __device__ __forceinline__

// ----- PTX helpers (sm_80-era; required for plain sm_100 ptxas target) ------
DEVINL uint32_t smem_u32(const void* p) {
    uint32_t a;
    asm("{ .reg .u64 t; cvta.to.shared.u64 t, %1; cvt.u32.u64 %0, t; }"
        : "=r"(a) : "l"(p));
    return a;
}
DEVINL void cp16(uint32_t sdst, const void* gsrc) {
    asm volatile("cp.async.cg.shared.global [%0], [%1], 16;"
                 :: "r"(sdst), "l"(__cvta_generic_to_global(gsrc)) : "memory");
}
DEVINL void cp_commit() { asm volatile("cp.async.commit_group;" ::: "memory"); }
template <int N>
DEVINL void cp_wait() { asm volatile("cp.async.wait_group %0;" :: "n"(N) : "memory"); }

DEVINL void ldm4(uint32_t* r, uint32_t addr) {
    asm volatile("ldmatrix.sync.aligned.m8n8.x4.shared.b16 {%0,%1,%2,%3}, [%4];"
                 : "=r"(r[0]), "=r"(r[1]), "=r"(r[2]), "=r"(r[3]) : "r"(addr));
}
DEVINL void mma16816(float* c, const uint32_t* a, const uint32_t* b) {
    asm volatile(
        "mma.sync.aligned.m16n8k16.row.col.f32.f16.f16.f32 "
        "{%0,%1,%2,%3}, {%4,%5,%6,%7}, {%8,%9}, {%0,%1,%2,%3};"
        : "+f"(c[0]), "+f"(c[1]), "+f"(c[2]), "+f"(c[3])
        : "r"(a[0]), "r"(a[1]), "r"(a[2]), "r"(a[3]), "r"(b[0]), "r"(b[1]));
}

// XOR-swizzled smem tile: 128 rows x 64 B (32 fp16), no padding.
DEVINL uint32_t swz(int r, int ch) {
    return (uint32_t)(r * 64 + ((ch ^ ((r >> 1) & 3)) << 4));
}

#define T_CB     8192              /* 128 rows * 64 B */
#define OFF_B    T_CB
#define STAGE_B  (2 * T_CB)        /* 16384: A tile + B tile */
#define NSTAGE   4
#define SMEM_BYTES (NSTAGE * STAGE_B)   /* 65536/CTA; 2 CTAs/SM = 128 KB */

// Load 128 rows x 32 fp16 into swizzled smem tile; 128 threads, 4 cp16 each.
template <int RS>
DEVINL void stage_load(const __half* __restrict__ g, uint32_t sdst, int k0, int tid) {
#pragma unroll
    for (int u = 0; u < 4; u++) {
        int q = u * 128 + tid;
        int r = q >> 2, ch = q & 3;
        cp16(sdst + swz(r, ch), g + (size_t)r * RS + k0 + ch * 8);
    }
}

// One BK=32 stage of single-pass fp16 MMAs; warp tile 64x64.
DEVINL void compute_stage(uint32_t st, int wm, int wn, int lane, float c[4][8][4]) {
    const int grp = lane >> 3, lr = lane & 7;
    const int arow = wm + lr + (grp & 1) * 8;
    const int brow = wn + lr + (grp >> 1) * 8;
#pragma unroll
    for (int kh = 0; kh < 2; kh++) {
        const int ag = kh * 2 + (grp >> 1);
        const int bg = kh * 2 + (grp & 1);
        uint32_t a[4][4];
#pragma unroll
        for (int mt = 0; mt < 4; mt++)
            ldm4(a[mt], st + swz(arow + mt * 16, ag));
#pragma unroll
        for (int bt = 0; bt < 4; bt++) {
            uint32_t b[4];
            ldm4(b, st + OFF_B + swz(brow + bt * 16, bg));
#pragma unroll
            for (int mt = 0; mt < 4; mt++) {
                mma16816(c[mt][bt * 2],     a[mt], b);
                mma16816(c[mt][bt * 2 + 1], a[mt], b + 2);
            }
        }
    }
}

// ---------------------------------------------------------------------------
// Kernel 1: LayerNorm + projection -> fp16 operands (unscaled; 1/N in epilogue)
// ---------------------------------------------------------------------------
__global__ __launch_bounds__(256) void prep_kernel(
    const float* __restrict__ m, const float* __restrict__ gamma,
    const float* __restrict__ beta, const float* __restrict__ Wab)
{
    __shared__ float sW[2 * C_ * C_];
    __shared__ float sg[C_], sb[C_];
    const int tid = threadIdx.x;
    for (int i = tid; i < 2 * C_ * C_; i += 256) sW[i] = Wab[i];
    if (tid < C_) { sg[tid] = gamma[tid]; sb[tid] = beta[tid]; }
    __syncthreads();

    const int s = blockIdx.x;
    const int n = tid;
    const float* xp = m + ((size_t)s * NSEQ + n) * C_;

    float x[C_];
#pragma unroll
    for (int q = 0; q < C_ / 4; q++) {
        float4 v = reinterpret_cast<const float4*>(xp)[q];
        x[4*q+0] = v.x; x[4*q+1] = v.y; x[4*q+2] = v.z; x[4*q+3] = v.w;
    }
    float mu = 0.f;
#pragma unroll
    for (int c = 0; c < C_; c++) mu += x[c];
    mu *= (1.f / C_);
    float var = 0.f;
#pragma unroll
    for (int c = 0; c < C_; c++) { float d = x[c] - mu; var += d * d; }
    var *= (1.f / C_);
    const float rstd = rsqrtf(var + 1e-5f);
#pragma unroll
    for (int c = 0; c < C_; c++) x[c] = (x[c] - mu) * rstd * sg[c] + sb[c];

#pragma unroll 4
    for (int d = 0; d < C_; d++) {
        float acc = 0.f;
#pragma unroll
        for (int c = 0; c < C_; c++) acc += x[c] * sW[d * C_ + c];
        g_A[(size_t)(s * C_ + d) * NSEQ + n] = __float2half_rn(acc);
    }
#pragma unroll 4
    for (int d = 0; d < C_; d++) {
        float acc = 0.f;
#pragma unroll
        for (int c = 0; c < C_; c++) acc += x[c] * sW[(C_ + d) * C_ + c];
        g_B[(size_t)(s * C_ + d) * NSEQ + n] = __float2half_rn(acc);
    }
}

__global__ __launch_bounds__(256) void wconv_kernel(const float* __restrict__ W) {
    int i = blockIdx.x * 256 + threadIdx.x;
    g_W[i] = __float2half_rn(W[i]);
}

// ---------------------------------------------------------------------------
// Unified tensor-core GEMM: CTA tile 128x128, 4 warps of 64x64, fp16 1-pass.
// 4-stage cp.async pipeline (3-deep prefetch), one __syncthreads per stage.
// 2 CTAs/SM. Panel-split so the O panel (67 MB) stays L2-resident between
// the MODE-0 producer and MODE-1 consumer.
// MODE 0: A*B^T (scaled 1/N) -> permuted fp16 O; `poff` = panel column base.
// MODE 1: O*W^T + b -> out;  `poff` = panel row offset within each i-group.
// ---------------------------------------------------------------------------
template <int KD, int MODE>
__global__ __launch_bounds__(128, 2) void gemm_kernel(
    const float* __restrict__ bout, float* __restrict__ out, int poff)
{
    extern __shared__ __align__(128) char smem[];
    const uint32_t sbase = smem_u32(smem);
    const int tid = threadIdx.x, lane = tid & 31, w = tid >> 5;
    const int wm = (w >> 1) * 64, wn = (w & 1) * 64;
    const int row0 = (MODE == 0) ? blockIdx.y * 128
                                 : blockIdx.y * 256 + poff;   // i*256 + panel j0
    const int col0 = (MODE == 0) ? poff + blockIdx.x * 128 : 0;

    const __half *pA, *pB;
    if (MODE == 0) {
        pA = g_A + (size_t)row0 * KD;
        pB = g_B + (size_t)col0 * KD;
    } else {
        pA = g_O + (size_t)row0 * KD;
        pB = g_W;
    }

    float bias[16];
    if (MODE == 1) {
#pragma unroll
        for (int nt = 0; nt < 8; nt++) {
            const int col = wn + nt * 8 + (lane & 3) * 2;
            bias[nt * 2]     = bout[col];
            bias[nt * 2 + 1] = bout[col + 1];
        }
    }

    float c[4][8][4];
#pragma unroll
    for (int a = 0; a < 4; a++)
#pragma unroll
        for (int b = 0; b < 8; b++)
#pragma unroll
            for (int d = 0; d < 4; d++) c[a][b][d] = 0.f;

    const int NS = KD / 32;

    // prologue: stages 0..2 in flight
#pragma unroll
    for (int p = 0; p < 3; p++) {
        const uint32_t bp = sbase + (uint32_t)p * STAGE_B;
        stage_load<KD>(pA, bp,         p * 32, tid);
        stage_load<KD>(pB, bp + OFF_B, p * 32, tid);
        cp_commit();
    }

#pragma unroll 1
    for (int s = 0; s < NS; s++) {
        cp_wait<2>();          // stage s resident (s+1, s+2 may still fly)
        __syncthreads();       // all warps done reading the buffer we overwrite
        if (s + 3 < NS) {
            const uint32_t nb = sbase + (uint32_t)((s + 3) & 3) * STAGE_B;
            const int k0 = (s + 3) * 32;
            stage_load<KD>(pA, nb,         k0, tid);
            stage_load<KD>(pB, nb + OFF_B, k0, tid);
        }
        cp_commit();           // one group per iteration (empty in tail)
        compute_stage(sbase + (uint32_t)(s & 3) * STAGE_B, wm, wn, lane, c);
    }

    const int R0 = row0 + wm + (lane >> 2);
    if (MODE == 0) {
#pragma unroll
        for (int mt = 0; mt < 4; mt++) {
#pragma unroll
            for (int h = 0; h < 2; h++) {
                const int R = R0 + mt * 16 + h * 8;
                const int i = R >> 5, cc = R & 31;
                const size_t rowbase = (size_t)i * (S_ * KOUT) + (size_t)cc * C_;
#pragma unroll
                for (int nt = 0; nt < 8; nt++) {
                    const int Cc = col0 + wn + nt * 8 + (lane & 3) * 2;
                    const int j = Cc >> 5, dd = Cc & 31;
                    __half2 hv;
                    hv.x = __float2half_rn(c[mt][nt][h * 2 + 0] * (1.f / NSEQ));
                    hv.y = __float2half_rn(c[mt][nt][h * 2 + 1] * (1.f / NSEQ));
                    *reinterpret_cast<__half2*>(
                        g_O + rowbase + (size_t)j * KOUT + dd) = hv;
                }
            }
        }
    } else {
#pragma unroll
        for (int mt = 0; mt < 4; mt++) {
#pragma unroll
            for (int h = 0; h < 2; h++) {
                const int R = R0 + mt * 16 + h * 8;
#pragma unroll
                for (int nt = 0; nt < 8; nt++) {
                    const int col = wn + nt * 8 + (lane & 3) * 2;
                    float2 v;
                    v.x = c[mt][nt][h * 2 + 0] + bias[nt * 2];
                    v.y = c[mt][nt][h * 2 + 1] + bias[nt * 2 + 1];
                    *reinterpret_cast<float2*>(out + (size_t)R * CZ + col) = v;
                }
            }
        }
    }
}

// ---------------------------------------------------------------------------
extern "C" void kernel_launch(void* const* d_in, const int* in_sizes, int n_in,
                              void* d_out, int out_size)
{
    const float* m_si = (const float*)d_in[0];
    const float* gam  = (const float*)d_in[1];
    const float* bet  = (const float*)d_in[2];
    const float* Wab  = (const float*)d_in[3];
    const float* Wout = (const float*)d_in[4];
    const float* bout = (const float*)d_in[5];
    float* out = (float*)d_out;

    cudaFuncSetAttribute(gemm_kernel<NSEQ, 0>,
                         cudaFuncAttributeMaxDynamicSharedMemorySize, SMEM_BYTES);
    cudaFuncSetAttribute(gemm_kernel<KOUT, 1>,
                         cudaFuncAttributeMaxDynamicSharedMemorySize, SMEM_BYTES);

    prep_kernel<<<S_, 256>>>(m_si, gam, bet, Wab);
    wconv_kernel<<<512, 256>>>(Wout);

    // Panelled producer/consumer: O panel (67 MB) stays resident in L2.
    for (int p = 0; p < S_ / JPAN; p++) {
        // gemm2 panel: all 8192 rows x (JPAN*32 = 4096) cols
        gemm_kernel<NSEQ, 0><<<dim3(JPAN * C_ / 128, 64), 128, SMEM_BYTES>>>(
            nullptr, nullptr, p * JPAN * C_);
        // gemm3 panel: rows i*256 + p*JPAN + [0,JPAN) for every i
        gemm_kernel<KOUT, 1><<<dim3(1, S_), 128, SMEM_BYTES>>>(
            bout, out, p * JPAN);
    }
}

// round 13
// speedup vs baseline: 1.0906x; 1.0906x over previous
#include <cuda_runtime.h>
#include <cuda_fp16.h>
#include <cstdint>
#include <cstddef>

#define S_    256
#define NSEQ  256
#define C_    32
#define CZ    128
#define SC    8192      /* S*C */
#define KOUT  1024      /* C*C */

// ----- scratch (__device__ globals; allocation-free rule) -------------------
__device__ __align__(16) __half g_A[SC * NSEQ];               // 4 MB, K-major (unscaled)
__device__ __align__(16) __half g_B[SC * NSEQ];               // 4 MB
__device__ __align__(16) __half g_O[(size_t)S_ * S_ * KOUT];  // 134 MB
__device__ __align__(16) __half g_W[CZ * KOUT];               // 256 KB

#define DEVINL __device__ __forceinline__

// ----- PTX helpers (sm_80-era; required for plain sm_100 ptxas target) ------
DEVINL uint32_t smem_u32(const void* p) {
    uint32_t a;
    asm("{ .reg .u64 t; cvta.to.shared.u64 t, %1; cvt.u32.u64 %0, t; }"
        : "=r"(a) : "l"(p));
    return a;
}
DEVINL void cp16(uint32_t sdst, const void* gsrc) {
    asm volatile("cp.async.cg.shared.global [%0], [%1], 16;"
                 :: "r"(sdst), "l"(__cvta_generic_to_global(gsrc)) : "memory");
}
DEVINL void cp_commit() { asm volatile("cp.async.commit_group;" ::: "memory"); }
template <int N>
DEVINL void cp_wait() { asm volatile("cp.async.wait_group %0;" :: "n"(N) : "memory"); }

DEVINL void ldm4(uint32_t* r, uint32_t addr) {
    asm volatile("ldmatrix.sync.aligned.m8n8.x4.shared.b16 {%0,%1,%2,%3}, [%4];"
                 : "=r"(r[0]), "=r"(r[1]), "=r"(r[2]), "=r"(r[3]) : "r"(addr));
}
DEVINL void mma16816(float* c, const uint32_t* a, const uint32_t* b) {
    asm volatile(
        "mma.sync.aligned.m16n8k16.row.col.f32.f16.f16.f32 "
        "{%0,%1,%2,%3}, {%4,%5,%6,%7}, {%8,%9}, {%0,%1,%2,%3};"
        : "+f"(c[0]), "+f"(c[1]), "+f"(c[2]), "+f"(c[3])
        : "r"(a[0]), "r"(a[1]), "r"(a[2]), "r"(a[3]), "r"(b[0]), "r"(b[1]));
}

// XOR-swizzled smem tile: 128 rows x 128 B (64 fp16).
// chunk ch (16B) at row r -> slot (ch ^ (r & 7)). 8 consecutive rows with a
// fixed ch hit 8 distinct 16B groups -> conflict-free ldmatrix; stores balanced.
DEVINL uint32_t swz(int r, int ch) {
    return (uint32_t)(r * 128 + ((ch ^ (r & 7)) << 4));
}

#define T_CB     16384             /* 128 rows * 128 B */
#define OFF_B    T_CB
#define STAGE_B  (2 * T_CB)        /* 32768: A tile + B tile (BK=64) */
#define NSTAGE   3
#define SMEM_BYTES (NSTAGE * STAGE_B)   /* 98304/CTA; 2 CTAs/SM = 192 KB */

// Load 128 rows x 64 fp16 (BK=64) into swizzled smem; 128 threads, 8 cp16 each.
template <int RS>
DEVINL void stage_load(const __half* __restrict__ g, uint32_t sdst, int k0, int tid) {
#pragma unroll
    for (int u = 0; u < 8; u++) {
        int q = u * 128 + tid;
        int r = q >> 3, ch = q & 7;
        cp16(sdst + swz(r, ch), g + (size_t)r * RS + k0 + ch * 8);
    }
}

// One BK=64 stage of single-pass fp16 MMAs; warp tile 64x64.
DEVINL void compute_stage(uint32_t st, int wm, int wn, int lane, float c[4][8][4]) {
    const int grp = lane >> 3, lr = lane & 7;
    const int arow = wm + lr + (grp & 1) * 8;
    const int brow = wn + lr + (grp >> 1) * 8;
#pragma unroll
    for (int kh = 0; kh < 4; kh++) {
        const int ag = kh * 2 + (grp >> 1);
        const int bg = kh * 2 + (grp & 1);
        uint32_t a[4][4];
#pragma unroll
        for (int mt = 0; mt < 4; mt++)
            ldm4(a[mt], st + swz(arow + mt * 16, ag));
#pragma unroll
        for (int bt = 0; bt < 4; bt++) {
            uint32_t b[4];
            ldm4(b, st + OFF_B + swz(brow + bt * 16, bg));
#pragma unroll
            for (int mt = 0; mt < 4; mt++) {
                mma16816(c[mt][bt * 2],     a[mt], b);
                mma16816(c[mt][bt * 2 + 1], a[mt], b + 2);
            }
        }
    }
}

// ---------------------------------------------------------------------------
// Kernel 1: LayerNorm + projection -> fp16 operands (unscaled; 1/N in epilogue)
// Grid (S_, 2): blockIdx.y = 0 produces A-half, 1 produces B-half.
// ---------------------------------------------------------------------------
__global__ __launch_bounds__(256) void prep_kernel(
    const float* __restrict__ m, const float* __restrict__ gamma,
    const float* __restrict__ beta, const float* __restrict__ Wab)
{
    __shared__ float sW[C_ * C_];
    __shared__ float sg[C_], sb[C_];
    const int tid = threadIdx.x;
    const int half = blockIdx.y;
    for (int i = tid; i < C_ * C_; i += 256) sW[i] = Wab[half * C_ * C_ + i];
    if (tid < C_) { sg[tid] = gamma[tid]; sb[tid] = beta[tid]; }
    __syncthreads();

    const int s = blockIdx.x;
    const int n = tid;
    const float* xp = m + ((size_t)s * NSEQ + n) * C_;

    float x[C_];
#pragma unroll
    for (int q = 0; q < C_ / 4; q++) {
        float4 v = reinterpret_cast<const float4*>(xp)[q];
        x[4*q+0] = v.x; x[4*q+1] = v.y; x[4*q+2] = v.z; x[4*q+3] = v.w;
    }
    float mu = 0.f;
#pragma unroll
    for (int c = 0; c < C_; c++) mu += x[c];
    mu *= (1.f / C_);
    float var = 0.f;
#pragma unroll
    for (int c = 0; c < C_; c++) { float d = x[c] - mu; var += d * d; }
    var *= (1.f / C_);
    const float rstd = rsqrtf(var + 1e-5f);
#pragma unroll
    for (int c = 0; c < C_; c++) x[c] = (x[c] - mu) * rstd * sg[c] + sb[c];

    __half* dst = half ? g_B : g_A;
#pragma unroll 4
    for (int d = 0; d < C_; d++) {
        float acc = 0.f;
#pragma unroll
        for (int c = 0; c < C_; c++) acc += x[c] * sW[d * C_ + c];
        dst[(size_t)(s * C_ + d) * NSEQ + n] = __float2half_rn(acc);
    }
}

__global__ __launch_bounds__(256) void wconv_kernel(const float* __restrict__ W) {
    int i = blockIdx.x * 256 + threadIdx.x;
    g_W[i] = __float2half_rn(W[i]);
}

// ---------------------------------------------------------------------------
// Unified tensor-core GEMM: CTA tile 128x128, 4 warps of 64x64, fp16 1-pass.
// BK=64, 3-stage cp.async pipeline (2-deep prefetch), one barrier per stage.
// 2 CTAs/SM. MODE 0: A*B^T (scaled 1/N) -> permuted fp16 O. MODE 1: O*W^T + b.
// ---------------------------------------------------------------------------
template <int KD, int MODE>
__global__ __launch_bounds__(128, 2) void gemm_kernel(
    const float* __restrict__ bout, float* __restrict__ out)
{
    extern __shared__ __align__(128) char smem[];
    const uint32_t sbase = smem_u32(smem);
    const int tid = threadIdx.x, lane = tid & 31, w = tid >> 5;
    const int wm = (w >> 1) * 64, wn = (w & 1) * 64;
    const int row0 = blockIdx.y * 128;
    const int col0 = blockIdx.x * 128;

    const __half *pA, *pB;
    if (MODE == 0) {
        pA = g_A + (size_t)row0 * KD;
        pB = g_B + (size_t)col0 * KD;
    } else {
        pA = g_O + (size_t)row0 * KD;
        pB = g_W;
    }

    float bias[16];
    if (MODE == 1) {
#pragma unroll
        for (int nt = 0; nt < 8; nt++) {
            const int col = wn + nt * 8 + (lane & 3) * 2;
            bias[nt * 2]     = bout[col];
            bias[nt * 2 + 1] = bout[col + 1];
        }
    }

    float c[4][8][4];
#pragma unroll
    for (int a = 0; a < 4; a++)
#pragma unroll
        for (int b = 0; b < 8; b++)
#pragma unroll
            for (int d = 0; d < 4; d++) c[a][b][d] = 0.f;

    const int NS = KD / 64;

    // prologue: stages 0..1 in flight
#pragma unroll
    for (int p = 0; p < 2; p++) {
        const uint32_t bp = sbase + (uint32_t)p * STAGE_B;
        stage_load<KD>(pA, bp,         p * 64, tid);
        stage_load<KD>(pB, bp + OFF_B, p * 64, tid);
        cp_commit();
    }

    int rd = 0, wr = 2;   // stage indices mod 3
#pragma unroll 1
    for (int s = 0; s < NS; s++) {
        cp_wait<1>();          // stage s resident (s+1 may still fly)
        __syncthreads();       // all warps done reading buffer we overwrite
        if (s + 2 < NS) {
            const uint32_t nb = sbase + (uint32_t)wr * STAGE_B;
            const int k0 = (s + 2) * 64;
            stage_load<KD>(pA, nb,         k0, tid);
            stage_load<KD>(pB, nb + OFF_B, k0, tid);
        }
        cp_commit();           // one group per iteration (empty in tail)
        compute_stage(sbase + (uint32_t)rd * STAGE_B, wm, wn, lane, c);
        rd = (rd == 2) ? 0 : rd + 1;
        wr = (wr == 2) ? 0 : wr + 1;
    }

    const int R0 = row0 + wm + (lane >> 2);
    if (MODE == 0) {
#pragma unroll
        for (int mt = 0; mt < 4; mt++) {
#pragma unroll
            for (int h = 0; h < 2; h++) {
                const int R = R0 + mt * 16 + h * 8;
                const int i = R >> 5, cc = R & 31;
                const size_t rowbase = (size_t)i * (S_ * KOUT) + (size_t)cc * C_;
#pragma unroll
                for (int nt = 0; nt < 8; nt++) {
                    const int Cc = col0 + wn + nt * 8 + (lane & 3) * 2;
                    const int j = Cc >> 5, dd = Cc & 31;
                    __half2 hv;
                    hv.x = __float2half_rn(c[mt][nt][h * 2 + 0] * (1.f / NSEQ));
                    hv.y = __float2half_rn(c[mt][nt][h * 2 + 1] * (1.f / NSEQ));
                    *reinterpret_cast<__half2*>(
                        g_O + rowbase + (size_t)j * KOUT + dd) = hv;
                }
            }
        }
    } else {
#pragma unroll
        for (int mt = 0; mt < 4; mt++) {
#pragma unroll
            for (int h = 0; h < 2; h++) {
                const int R = R0 + mt * 16 + h * 8;
#pragma unroll
                for (int nt = 0; nt < 8; nt++) {
                    const int col = wn + nt * 8 + (lane & 3) * 2;
                    float2 v;
                    v.x = c[mt][nt][h * 2 + 0] + bias[nt * 2];
                    v.y = c[mt][nt][h * 2 + 1] + bias[nt * 2 + 1];
                    *reinterpret_cast<float2*>(out + (size_t)R * CZ + col) = v;
                }
            }
        }
    }
}

// ---------------------------------------------------------------------------
extern "C" void kernel_launch(void* const* d_in, const int* in_sizes, int n_in,
                              void* d_out, int out_size)
{
    const float* m_si = (const float*)d_in[0];
    const float* gam  = (const float*)d_in[1];
    const float* bet  = (const float*)d_in[2];
    const float* Wab  = (const float*)d_in[3];
    const float* Wout = (const float*)d_in[4];
    const float* bout = (const float*)d_in[5];
    float* out = (float*)d_out;

    cudaFuncSetAttribute(gemm_kernel<NSEQ, 0>,
                         cudaFuncAttributeMaxDynamicSharedMemorySize, SMEM_BYTES);
    cudaFuncSetAttribute(gemm_kernel<KOUT, 1>,
                         cudaFuncAttributeMaxDynamicSharedMemorySize, SMEM_BYTES);

    prep_kernel<<<dim3(S_, 2), 256>>>(m_si, gam, bet, Wab);
    wconv_kernel<<<512, 256>>>(Wout);
    gemm_kernel<NSEQ, 0><<<dim3(64, 64), 128, SMEM_BYTES>>>(nullptr, nullptr);
    gemm_kernel<KOUT, 1><<<dim3(1, 512), 128, SMEM_BYTES>>>(bout, out);
}